// round 5
// baseline (speedup 1.0000x reference)
#include <cuda_runtime.h>
#include <math.h>

typedef unsigned long long u64;
#define FULL 0xFFFFFFFFu

// ---------------- f32x2 helpers (packed fp32 FMA, 2x FFMA rate on sm_103a) ----
__device__ __forceinline__ void ffma2(u64 &d, u64 a, u64 b){
    asm("fma.rn.f32x2 %0, %1, %2, %0;" : "+l"(d) : "l"(a), "l"(b));
}
__device__ __forceinline__ u64 pk2(float a, float b){
    u64 r; asm("mov.b64 %0, {%1, %2};" : "=l"(r) : "f"(a), "f"(b)); return r;
}
__device__ __forceinline__ float2 up2(u64 v){
    float2 f; asm("mov.b64 {%0, %1}, %2;" : "=f"(f.x), "=f"(f.y) : "l"(v)); return f;
}
union F4U { float4 f; u64 u[2]; };

// ---------------- scratch (device globals; no allocs allowed) ----------------
__device__ float g_tr[(size_t)16*128*128*64];    // lowres transposed (n,y,x,ci)      67MB
__device__ float g_tl[(size_t)16*128*128*128];   // conv1 out low-res (n,y,x,c)      134MB
__device__ float g_lg[(size_t)16*32*256*256];    // conv2 logits (n,o,h,w)           134MB
__device__ float g_gx[(size_t)16*16*256*256];    // sample x coord (pixels)           67MB
__device__ float g_gy[(size_t)16*16*256*256];    // sample y coord (pixels)           67MB
__device__ float g_p1[16*256*128];               // per-(n,row) channel sums
__device__ float g_p2[16*256*128];               // per-(n,row) channel sumsq
__device__ u64   g_w2p[16*2048];                 // folded conv2 weights (o, cpair)
__device__ float g_b2[16*32];                    // folded conv2 bias

// ============ k_tr: lowres (n,ci,y,x) planar -> g_tr (n,y,x,ci) channel-last ====
__global__ __launch_bounds__(256) void k_tr(const float* __restrict__ lo){
    __shared__ float s[64][133];
    int n = blockIdx.x >> 7, y = blockIdx.x & 127;
    const float* inb = lo + (size_t)n*64*128*128 + (size_t)y*128;
    for (int i = threadIdx.x; i < 64*32; i += 256){
        int ci = i >> 5, x4 = (i & 31) * 4;
        float4 v = *(const float4*)(inb + (size_t)ci*16384 + x4);
        s[ci][x4] = v.x; s[ci][x4+1] = v.y; s[ci][x4+2] = v.z; s[ci][x4+3] = v.w;
    }
    __syncthreads();
    float* outb = g_tr + ((size_t)(n*128 + y)*128)*64;
    for (int i = threadIdx.x; i < 128*16; i += 256){
        int x = i >> 4, c4 = (i & 15) * 4;
        float4 v = make_float4(s[c4][x], s[c4+1][x], s[c4+2][x], s[c4+3][x]);
        *(float4*)(outb + x*64 + c4) = v;
    }
}

// ============ k_conv1: 1x1 conv (64->128) at LOW res, f32x2 =====================
__global__ __launch_bounds__(256) void k_conv1(const float* __restrict__ w1,
                                               const float* __restrict__ bias){
    __shared__ __align__(16) u64 ws[2048];   // 64 o x 32 cpairs
    int n = blockIdx.x >> 7, y = blockIdx.x & 127, oh = blockIdx.y;
    const u64* w64 = (const u64*)w1;
    for (int i = threadIdx.x; i < 2048; i += 256) ws[i] = w64[oh*2048 + i];
    __syncthreads();
    int pxg = threadIdx.x >> 2, og = threadIdx.x & 3;
    const float* inb = g_tr + ((size_t)(n*128 + y)*128 + pxg*2)*64;
    u64 acc[2][16];
    #pragma unroll
    for (int p = 0; p < 2; p++)
        #pragma unroll
        for (int j = 0; j < 16; j++) acc[p][j] = 0ull;
    #pragma unroll 4
    for (int c = 0; c < 64; c += 4){
        F4U a0, a1;
        a0.f = *(const float4*)(inb + c);
        a1.f = *(const float4*)(inb + 64 + c);
        int cp = c >> 1;
        #pragma unroll
        for (int j = 0; j < 16; j++){
            ulonglong2 wv = *(const ulonglong2*)&ws[(og*16 + j)*32 + cp];
            ffma2(acc[0][j], a0.u[0], wv.x); ffma2(acc[0][j], a0.u[1], wv.y);
            ffma2(acc[1][j], a1.u[0], wv.x); ffma2(acc[1][j], a1.u[1], wv.y);
        }
    }
    int obase = oh*64 + og*16;
    float* outb = g_tl + ((size_t)(n*128 + y)*128 + pxg*2)*128 + obase;
    #pragma unroll
    for (int p = 0; p < 2; p++){
        float res[16];
        #pragma unroll
        for (int j = 0; j < 16; j++){
            float2 f = up2(acc[p][j]);
            res[j] = f.x + f.y + __ldg(&bias[obase + j]);
        }
        #pragma unroll
        for (int j4 = 0; j4 < 4; j4++)
            *(float4*)(outb + p*128 + j4*4) =
                make_float4(res[j4*4], res[j4*4+1], res[j4*4+2], res[j4*4+3]);
    }
}

// ============ k_stat: upsample+GELU (no store) -> per-(n,row) channel partials ==
__global__ __launch_bounds__(256) void k_stat(){
    __shared__ float sm[256];
    int n = blockIdx.x >> 8, oy = blockIdx.x & 255;
    float ysf = oy * (127.0f/255.0f);
    float yf  = floorf(ysf);
    int y0 = (int)yf, y1 = min(y0 + 1, 127);
    float wy = ysf - yf;
    int c = threadIdx.x & 127, half = threadIdx.x >> 7;
    const float* r0 = g_tl + ((size_t)(n*128 + y0)*128)*128 + c;
    const float* r1 = g_tl + ((size_t)(n*128 + y1)*128)*128 + c;
    float s1 = 0.f, s2 = 0.f;
    for (int i = 0; i < 128; i++){
        int ox = half*128 + i;
        float xs = ox * (127.0f/255.0f);
        float xf = floorf(xs);
        int x0 = (int)xf, x1 = min(x0 + 1, 127);
        float wx = xs - xf;
        float v0 = __ldg(r0 + (size_t)x0*128)*(1.f - wx) + __ldg(r0 + (size_t)x1*128)*wx;
        float v1 = __ldg(r1 + (size_t)x0*128)*(1.f - wx) + __ldg(r1 + (size_t)x1*128)*wx;
        float v  = v0*(1.f - wy) + v1*wy;
        float ge = 0.5f*v*(1.f + erff(v*0.70710678118654752f));
        s1 += ge; s2 += ge*ge;
    }
    sm[threadIdx.x] = s1; __syncthreads();
    if (half == 0) g_p1[((size_t)n*256 + oy)*128 + c] = sm[c] + sm[c+128];
    __syncthreads();
    sm[threadIdx.x] = s2; __syncthreads();
    if (half == 0) g_p2[((size_t)n*256 + oy)*128 + c] = sm[c] + sm[c+128];
}

// ============ k_fold: GN stats + SE + fold into conv2 weights/bias (1024 thr) ===
__global__ __launch_bounds__(1024) void k_fold(const float* __restrict__ gnw,
        const float* __restrict__ gnb, const float* __restrict__ sw1,
        const float* __restrict__ sw2, const float* __restrict__ w2){
    int n = blockIdx.x;
    __shared__ float sc[1024];
    __shared__ float sum[128], ssq[128], mr[128], Aa[128], Bb[128], y1s[16], mu[2], inv[2];
    int c = threadIdx.x & 127, grp = threadIdx.x >> 7;   // 8 groups x 32 rows
    float a = 0.f;
    for (int r = grp*32; r < grp*32 + 32; r++) a += g_p1[((size_t)n*256 + r)*128 + c];
    sc[threadIdx.x] = a; __syncthreads();
    if (threadIdx.x < 128){
        float t = 0.f;
        #pragma unroll
        for (int g = 0; g < 8; g++) t += sc[g*128 + c];
        sum[c] = t;
    }
    __syncthreads();
    a = 0.f;
    for (int r = grp*32; r < grp*32 + 32; r++) a += g_p2[((size_t)n*256 + r)*128 + c];
    sc[threadIdx.x] = a; __syncthreads();
    if (threadIdx.x < 128){
        float t = 0.f;
        #pragma unroll
        for (int g = 0; g < 8; g++) t += sc[g*128 + c];
        ssq[c] = t;
    }
    __syncthreads();
    if (threadIdx.x < 2){
        float S = 0.f, Q = 0.f;
        for (int i = 0; i < 64; i++){ S += sum[threadIdx.x*64 + i]; Q += ssq[threadIdx.x*64 + i]; }
        float mean = S * (1.f/(64.f*65536.f));
        float var  = Q * (1.f/(64.f*65536.f)) - mean*mean;
        mu[threadIdx.x] = mean; inv[threadIdx.x] = rsqrtf(var + 1e-5f);
    }
    __syncthreads();
    if (threadIdx.x < 128){
        int g = c >> 6;
        float mc = sum[c] * (1.f/65536.f);
        mr[c] = (mc - mu[g]) * inv[g] * gnw[c] + gnb[c];
    }
    __syncthreads();
    if (threadIdx.x < 16){
        float acc = 0.f;
        for (int i = 0; i < 128; i++) acc += mr[i] * sw1[threadIdx.x*128 + i];
        y1s[threadIdx.x] = fmaxf(acc, 0.f);
    }
    __syncthreads();
    if (threadIdx.x < 128){
        float t = 0.f;
        for (int j = 0; j < 16; j++) t += y1s[j] * sw2[c*16 + j];
        float sg = 1.f/(1.f + expf(-t));
        int g = c >> 6;
        Aa[c] = inv[g]*gnw[c]*sg;
        Bb[c] = (gnb[c] - mu[g]*inv[g]*gnw[c])*sg;
    }
    __syncthreads();
    for (int i = threadIdx.x; i < 2048; i += 1024){
        int o = i >> 6, cp = i & 63, c0 = cp*2;
        g_w2p[n*2048 + i] = pk2(w2[o*128 + c0]*Aa[c0], w2[o*128 + c0 + 1]*Aa[c0 + 1]);
    }
    if (threadIdx.x < 32){
        float bb = 0.f;
        for (int i = 0; i < 128; i++) bb += w2[threadIdx.x*128 + i] * Bb[i];
        g_b2[n*32 + threadIdx.x] = bb;
    }
}

// ============ k_upconv2: FUSED upsample+GELU (smem tile) + folded conv (f32x2) ==
// grid 16384: n = b>>10, oy = (b>>2)&255, q = b&3 (64-px quarter row)
__global__ __launch_bounds__(256) void k_upconv2(){
    __shared__ float ge[64*128];             // 32KB GELU tile (px-major, ch-last)
    __shared__ __align__(16) u64 ws[2048];   // 16KB folded weights (32 o x 64 cp)
    int b = blockIdx.x;
    int n = b >> 10, oy = (b >> 2) & 255, q = b & 3;
    for (int i = threadIdx.x; i < 2048; i += 256) ws[i] = g_w2p[n*2048 + i];

    // phase 1: 64 px x 128 ch GELU tile
    float ysf = oy * (127.0f/255.0f);
    float yf  = floorf(ysf);
    int y0 = (int)yf, y1 = min(y0 + 1, 127);
    float wy = ysf - yf;
    int c = threadIdx.x & 127, xg = threadIdx.x >> 7;    // 2 groups x 32 px
    const float* r0 = g_tl + ((size_t)(n*128 + y0)*128)*128 + c;
    const float* r1 = g_tl + ((size_t)(n*128 + y1)*128)*128 + c;
    #pragma unroll 4
    for (int i = 0; i < 32; i++){
        int pl = xg*32 + i;                  // local px 0..63
        int ox = q*64 + pl;
        float xs = ox * (127.0f/255.0f);
        float xf = floorf(xs);
        int x0 = (int)xf, x1 = min(x0 + 1, 127);
        float wx = xs - xf;
        float v0 = __ldg(r0 + (size_t)x0*128)*(1.f - wx) + __ldg(r0 + (size_t)x1*128)*wx;
        float v1 = __ldg(r1 + (size_t)x0*128)*(1.f - wx) + __ldg(r1 + (size_t)x1*128)*wx;
        float v  = v0*(1.f - wy) + v1*wy;
        ge[pl*128 + c] = 0.5f*v*(1.f + erff(v*0.70710678118654752f));
    }
    __syncthreads();

    // phase 2: conv 128->32 on 64 px; thread = (px, og of 8 o)
    int px = threadIdx.x >> 2, og = threadIdx.x & 3;
    u64 acc[8];
    #pragma unroll
    for (int j = 0; j < 8; j++) acc[j] = 0ull;
    const float* gp = &ge[px*128];
    #pragma unroll 4
    for (int cc = 0; cc < 128; cc += 4){
        F4U a; a.f = *(const float4*)(gp + cc);
        int cp = cc >> 1;
        #pragma unroll
        for (int j = 0; j < 8; j++){
            ulonglong2 wv = *(const ulonglong2*)&ws[(og*8 + j)*64 + cp];
            ffma2(acc[j], a.u[0], wv.x);
            ffma2(acc[j], a.u[1], wv.y);
        }
    }
    #pragma unroll
    for (int j = 0; j < 8; j++){
        int o = og*8 + j;
        float2 f = up2(acc[j]);
        g_lg[((size_t)(n*32 + o))*65536 + (size_t)oy*256 + q*64 + px] =
            f.x + f.y + __ldg(&g_b2[n*32 + o]);
    }
}

// ============ k_softx: per-row softmax+cumsum (channel 2*hd) -> gy coord ========
__global__ __launch_bounds__(256) void k_softx(){
    int lane = threadIdx.x & 31, wid = threadIdx.x >> 5;
    int R = blockIdx.x*8 + wid;          // (p<<8)|y
    int p = R >> 8, y = R & 255;
    int n = p >> 4, hd = p & 15;
    const float* src = g_lg + ((size_t)(n*32 + 2*hd)*256 + y)*256 + lane*8;
    float v[8];
    {
        float4 A = *(const float4*)src, B = *(const float4*)(src + 4);
        v[0]=A.x; v[1]=A.y; v[2]=A.z; v[3]=A.w;
        v[4]=B.x; v[5]=B.y; v[6]=B.z; v[7]=B.w;
    }
    float m = v[0];
    #pragma unroll
    for (int i = 1; i < 8; i++) m = fmaxf(m, v[i]);
    #pragma unroll
    for (int off = 16; off >= 1; off >>= 1) m = fmaxf(m, __shfl_xor_sync(FULL, m, off));
    float ls = 0.f;
    #pragma unroll
    for (int i = 0; i < 8; i++){ v[i] = expf(v[i] - m); ls += v[i]; }
    float pre = ls;
    #pragma unroll
    for (int off = 1; off < 32; off <<= 1){
        float t = __shfl_up_sync(FULL, pre, off);
        if (lane >= off) pre += t;
    }
    float total = __shfl_sync(FULL, pre, 31);
    float run = pre - ls;
    float sc = 255.f / total;
    float o[8];
    #pragma unroll
    for (int i = 0; i < 8; i++){ run += v[i]; o[i] = run * sc; }
    float* dst = g_gy + (size_t)p*65536 + y*256 + lane*8;
    *(float4*)dst       = make_float4(o[0], o[1], o[2], o[3]);
    *(float4*)(dst + 4) = make_float4(o[4], o[5], o[6], o[7]);
}

// ============ k_softy: per-col softmax+cumsum, 4 row-chunks x 1024 thr ==========
__global__ __launch_bounds__(1024) void k_softy(){
    __shared__ float pm[4][256], ps[4][256];
    int pb = blockIdx.x;
    int n = pb >> 4, hd = pb & 15;
    int col = threadIdx.x & 255, ch = threadIdx.x >> 8;   // 4 chunks x 64 rows
    const float* src = g_lg + ((size_t)(n*32 + 2*hd + 1)*256)*256 + col;
    float m = -1e30f;
    for (int y = ch*64; y < ch*64 + 64; y++) m = fmaxf(m, __ldg(src + (size_t)y*256));
    pm[ch][col] = m; __syncthreads();
    m = fmaxf(fmaxf(pm[0][col], pm[1][col]), fmaxf(pm[2][col], pm[3][col]));
    float s = 0.f;
    for (int y = ch*64; y < ch*64 + 64; y++) s += expf(__ldg(src + (size_t)y*256) - m);
    ps[ch][col] = s; __syncthreads();
    float tot = ps[0][col] + ps[1][col] + ps[2][col] + ps[3][col];
    float run = 0.f;
    for (int k = 0; k < 4; k++) if (k < ch) run += ps[k][col];
    float sc = 255.f / tot;
    float* dst = g_gx + (size_t)pb*65536 + col;
    for (int y = ch*64; y < ch*64 + 64; y++){
        run += expf(__ldg(src + (size_t)y*256) - m);
        dst[(size_t)y*256] = run * sc;
    }
}

// ============ k_sample: 32x32 tiles, lanes along y (coalesced gathers) ==========
__global__ __launch_bounds__(256) void k_sample(const float* __restrict__ hi,
                                                float* __restrict__ out){
    __shared__ float sgx[32][33], sgy[32][33], so[32][33];
    int b = blockIdx.x;                   // p*64 + tile
    int p = b >> 6, tile = b & 63;
    int y0 = (tile >> 3) * 32, x0 = (tile & 7) * 32;
    size_t base = (size_t)p*65536;
    {   // coalesced coord load: row-major float4s
        int row = threadIdx.x >> 3, c4 = (threadIdx.x & 7) * 4;
        size_t idx = base + (size_t)(y0 + row)*256 + x0 + c4;
        float4 a = *(const float4*)(g_gx + idx);
        float4 c = *(const float4*)(g_gy + idx);
        sgx[row][c4]=a.x; sgx[row][c4+1]=a.y; sgx[row][c4+2]=a.z; sgx[row][c4+3]=a.w;
        sgy[row][c4]=c.x; sgy[row][c4+1]=c.y; sgy[row][c4+2]=c.z; sgy[row][c4+3]=c.w;
    }
    __syncthreads();
    const float* s = hi + base;
    int yl = threadIdx.x & 31, xg = threadIdx.x >> 5;
    #pragma unroll
    for (int k = 0; k < 4; k++){
        int xl = xg*4 + k;
        float gx = sgx[yl][xl], gy = sgy[yl][xl];
        float xf = floorf(gx), yf = floorf(gy);
        float wx = gx - xf, wy = gy - yf;
        int ix0 = (int)xf, iy0 = (int)yf;
        int ix1 = ix0 + 1, iy1 = iy0 + 1;
        float mx0 = (ix0 >= 0 && ix0 <= 255) ? 1.f : 0.f;
        float mx1 = (ix1 >= 0 && ix1 <= 255) ? 1.f : 0.f;
        float my0 = (iy0 >= 0 && iy0 <= 255) ? 1.f : 0.f;
        float my1 = (iy1 >= 0 && iy1 <= 255) ? 1.f : 0.f;
        int cx0 = min(max(ix0, 0), 255), cx1 = min(max(ix1, 0), 255);
        int cy0 = min(max(iy0, 0), 255), cy1 = min(max(iy1, 0), 255);
        float v00 = __ldg(s + (size_t)cy0*256 + cx0);
        float v10 = __ldg(s + (size_t)cy0*256 + cx1);
        float v01 = __ldg(s + (size_t)cy1*256 + cx0);
        float v11 = __ldg(s + (size_t)cy1*256 + cx1);
        so[yl][xl] = v00*((1.f-wx)*(1.f-wy)*mx0*my0)
                   + v10*(wx*(1.f-wy)*mx1*my0)
                   + v01*((1.f-wx)*wy*mx0*my1)
                   + v11*(wx*wy*mx1*my1);
    }
    __syncthreads();
    {   // coalesced output store
        int row = threadIdx.x >> 3, c4 = (threadIdx.x & 7) * 4;
        size_t idx = base + (size_t)(y0 + row)*256 + x0 + c4;
        *(float4*)(out + idx) = make_float4(so[row][c4], so[row][c4+1],
                                            so[row][c4+2], so[row][c4+3]);
    }
}

// ================================ launch ========================================
extern "C" void kernel_launch(void* const* d_in, const int* in_sizes, int n_in,
                              void* d_out, int out_size){
    const float* lowres  = (const float*)d_in[0];
    const float* highres = (const float*)d_in[1];
    const float* conv1_w = (const float*)d_in[2];
    const float* conv1_b = (const float*)d_in[3];
    const float* gn_w    = (const float*)d_in[4];
    const float* gn_b    = (const float*)d_in[5];
    const float* se_w1   = (const float*)d_in[6];
    const float* se_w2   = (const float*)d_in[7];
    const float* conv2_w = (const float*)d_in[8];
    float* out = (float*)d_out;

    k_tr     <<<2048, 256>>>(lowres);
    k_conv1  <<<dim3(2048, 2), 256>>>(conv1_w, conv1_b);
    k_stat   <<<4096, 256>>>();
    k_fold   <<<16, 1024>>>(gn_w, gn_b, se_w1, se_w2, conv2_w);
    k_upconv2<<<16384, 256>>>();
    k_softx  <<<8192, 256>>>();
    k_softy  <<<256, 1024>>>();
    k_sample <<<16384, 256>>>(highres, out);
}

// round 7
// speedup vs baseline: 2.0061x; 2.0061x over previous
#include <cuda_runtime.h>
#include <math.h>

typedef unsigned long long u64;
#define FULL 0xFFFFFFFFu

// ---------------- f32x2 helpers (packed fp32 FMA, 2x FFMA rate on sm_103a) ----
__device__ __forceinline__ void ffma2(u64 &d, u64 a, u64 b){
    asm("fma.rn.f32x2 %0, %1, %2, %0;" : "+l"(d) : "l"(a), "l"(b));
}
__device__ __forceinline__ u64 pk2(float a, float b){
    u64 r; asm("mov.b64 %0, {%1, %2};" : "=l"(r) : "f"(a), "f"(b)); return r;
}
__device__ __forceinline__ float2 up2(u64 v){
    float2 f; asm("mov.b64 {%0, %1}, %2;" : "=f"(f.x), "=f"(f.y) : "l"(v)); return f;
}
union F4U { float4 f; u64 u[2]; };

// ---------------- scratch (device globals; no allocs allowed) ----------------
__device__ float g_tl[(size_t)16*128*128*128];   // conv1 out low-res (n,y,x,c)      134MB
__device__ float g_r [(size_t)16*256*256*128];   // gelu out (n,h,w,c)               537MB
__device__ float g_lg[(size_t)16*32*256*256];    // conv2 logits (n,o,h,w)           134MB
__device__ float g_gx[(size_t)16*16*256*256];    // sample x coord (pixels)           67MB
__device__ float g_gy[(size_t)16*16*256*256];    // sample y coord (pixels)           67MB
__device__ float g_p1[16*256*128];               // per-(n,row) channel sums
__device__ float g_p2[16*256*128];               // per-(n,row) channel sumsq
__device__ u64   g_w2p[16*2048];                 // folded conv2 weights ws[cp*32+o]
__device__ float g_b2[16*32];                    // folded conv2 bias

// ============ k_trconv1: fused transpose + 1x1 conv (64->128) at LOW res ========
// grid (2048, 2): (n*128+y, o-half). smem transpose of acts + interleaved weights.
__global__ __launch_bounds__(256) void k_trconv1(const float* __restrict__ lo,
                                                 const float* __restrict__ w1,
                                                 const float* __restrict__ bias){
    __shared__ float sa[64*129];             // acts sa[ci*129 + x], 33KB
    __shared__ __align__(16) u64 ws[2048];   // weights ws[cp*64 + oo], 16KB (64 o)
    int n = blockIdx.x >> 7, y = blockIdx.x & 127, oh = blockIdx.y;
    const float* inb = lo + ((size_t)n*64*128 + y)*128;
    for (int i = threadIdx.x; i < 2048; i += 256){
        int ci = i >> 5, x4 = (i & 31) * 4;
        float4 v = *(const float4*)(inb + (size_t)ci*16384 + x4);
        sa[ci*129 + x4] = v.x; sa[ci*129 + x4+1] = v.y;
        sa[ci*129 + x4+2] = v.z; sa[ci*129 + x4+3] = v.w;
    }
    for (int i = threadIdx.x; i < 2048; i += 256){
        int cp = i >> 6, oo = i & 63;
        int o = oh*64 + oo;
        ws[i] = pk2(__ldg(&w1[o*64 + cp*2]), __ldg(&w1[o*64 + cp*2 + 1]));
    }
    __syncthreads();
    int pxg = threadIdx.x >> 2, og = threadIdx.x & 3;   // 2 px, 16 o each
    int x0 = pxg*2;
    u64 acc[2][16];
    #pragma unroll
    for (int p = 0; p < 2; p++)
        #pragma unroll
        for (int j = 0; j < 16; j++) acc[p][j] = 0ull;
    #pragma unroll 4
    for (int ci = 0; ci < 64; ci += 2){
        int cp = ci >> 1;
        u64 a0 = pk2(sa[ci*129 + x0],     sa[(ci+1)*129 + x0]);
        u64 a1 = pk2(sa[ci*129 + x0 + 1], sa[(ci+1)*129 + x0 + 1]);
        const u64* wp = &ws[cp*64 + og*16];
        #pragma unroll
        for (int j2 = 0; j2 < 8; j2++){
            ulonglong2 wv = *(const ulonglong2*)(wp + j2*2);
            ffma2(acc[0][2*j2],   a0, wv.x); ffma2(acc[0][2*j2+1], a0, wv.y);
            ffma2(acc[1][2*j2],   a1, wv.x); ffma2(acc[1][2*j2+1], a1, wv.y);
        }
    }
    int obase = oh*64 + og*16;
    float* outb = g_tl + ((size_t)(n*128 + y)*128 + x0)*128 + obase;
    #pragma unroll
    for (int p = 0; p < 2; p++){
        float res[16];
        #pragma unroll
        for (int j = 0; j < 16; j++){
            float2 f = up2(acc[p][j]);
            res[j] = f.x + f.y + __ldg(&bias[obase + j]);
        }
        #pragma unroll
        for (int j4 = 0; j4 < 4; j4++)
            *(float4*)(outb + p*128 + j4*4) =
                make_float4(res[j4*4], res[j4*4+1], res[j4*4+2], res[j4*4+3]);
    }
}

// ============ k_up: bilinear 128->256 + exact GELU -> g_r + partial stats =======
__global__ __launch_bounds__(256) void k_up(){
    __shared__ float sm[256];
    int n = blockIdx.x >> 8, oy = blockIdx.x & 255;
    float ysf = oy * (127.0f/255.0f);
    float yf  = floorf(ysf);
    int y0 = (int)yf, y1 = min(y0 + 1, 127);
    float wy = ysf - yf;
    int c = threadIdx.x & 127, half = threadIdx.x >> 7;
    const float* r0 = g_tl + ((size_t)(n*128 + y0)*128)*128 + c;
    const float* r1 = g_tl + ((size_t)(n*128 + y1)*128)*128 + c;
    float* outb = g_r + ((size_t)(n*256 + oy)*256)*128 + c;
    float s1 = 0.f, s2 = 0.f;
    for (int i = 0; i < 128; i++){
        int ox = half*128 + i;
        float xs = ox * (127.0f/255.0f);
        float xf = floorf(xs);
        int x0 = (int)xf, x1 = min(x0 + 1, 127);
        float wx = xs - xf;
        float v0 = __ldg(r0 + (size_t)x0*128)*(1.f - wx) + __ldg(r0 + (size_t)x1*128)*wx;
        float v1 = __ldg(r1 + (size_t)x0*128)*(1.f - wx) + __ldg(r1 + (size_t)x1*128)*wx;
        float v  = v0*(1.f - wy) + v1*wy;
        float ge = 0.5f*v*(1.f + erff(v*0.70710678118654752f));
        outb[(size_t)ox*128] = ge;
        s1 += ge; s2 += ge*ge;
    }
    sm[threadIdx.x] = s1; __syncthreads();
    if (half == 0) g_p1[((size_t)n*256 + oy)*128 + c] = sm[c] + sm[c+128];
    __syncthreads();
    sm[threadIdx.x] = s2; __syncthreads();
    if (half == 0) g_p2[((size_t)n*256 + oy)*128 + c] = sm[c] + sm[c+128];
}

// ============ k_fold: GN stats + SE -> folded conv2 weights (interleaved) =======
__global__ __launch_bounds__(1024) void k_fold(const float* __restrict__ gnw,
        const float* __restrict__ gnb, const float* __restrict__ sw1,
        const float* __restrict__ sw2, const float* __restrict__ w2){
    int n = blockIdx.x;
    __shared__ float sc[1024];
    __shared__ float sum[128], ssq[128], mr[128], Aa[128], Bb[128], y1s[16], mu[2], inv[2];
    int c = threadIdx.x & 127, grp = threadIdx.x >> 7;
    float a = 0.f;
    for (int r = grp*32; r < grp*32 + 32; r++) a += g_p1[((size_t)n*256 + r)*128 + c];
    sc[threadIdx.x] = a; __syncthreads();
    if (threadIdx.x < 128){
        float t = 0.f;
        #pragma unroll
        for (int g = 0; g < 8; g++) t += sc[g*128 + c];
        sum[c] = t;
    }
    __syncthreads();
    a = 0.f;
    for (int r = grp*32; r < grp*32 + 32; r++) a += g_p2[((size_t)n*256 + r)*128 + c];
    sc[threadIdx.x] = a; __syncthreads();
    if (threadIdx.x < 128){
        float t = 0.f;
        #pragma unroll
        for (int g = 0; g < 8; g++) t += sc[g*128 + c];
        ssq[c] = t;
    }
    __syncthreads();
    if (threadIdx.x < 2){
        float S = 0.f, Q = 0.f;
        for (int i = 0; i < 64; i++){ S += sum[threadIdx.x*64 + i]; Q += ssq[threadIdx.x*64 + i]; }
        float mean = S * (1.f/(64.f*65536.f));
        float var  = Q * (1.f/(64.f*65536.f)) - mean*mean;
        mu[threadIdx.x] = mean; inv[threadIdx.x] = rsqrtf(var + 1e-5f);
    }
    __syncthreads();
    if (threadIdx.x < 128){
        int g = c >> 6;
        float mc = sum[c] * (1.f/65536.f);
        mr[c] = (mc - mu[g]) * inv[g] * gnw[c] + gnb[c];
    }
    __syncthreads();
    if (threadIdx.x < 16){
        float acc = 0.f;
        for (int i = 0; i < 128; i++) acc += mr[i] * sw1[threadIdx.x*128 + i];
        y1s[threadIdx.x] = fmaxf(acc, 0.f);
    }
    __syncthreads();
    if (threadIdx.x < 128){
        float t = 0.f;
        for (int j = 0; j < 16; j++) t += y1s[j] * sw2[c*16 + j];
        float sg = 1.f/(1.f + expf(-t));
        int g = c >> 6;
        Aa[c] = inv[g]*gnw[c]*sg;
        Bb[c] = (gnb[c] - mu[g]*inv[g]*gnw[c])*sg;
    }
    __syncthreads();
    // interleaved: g_w2p[n*2048 + cp*32 + o]
    for (int i = threadIdx.x; i < 2048; i += 1024){
        int cp = i >> 5, o = i & 31, c0 = cp*2;
        g_w2p[n*2048 + i] = pk2(w2[o*128 + c0]*Aa[c0], w2[o*128 + c0 + 1]*Aa[c0 + 1]);
    }
    if (threadIdx.x < 32){
        float bb = 0.f;
        for (int i = 0; i < 128; i++) bb += w2[threadIdx.x*128 + i] * Bb[i];
        g_b2[n*32 + threadIdx.x] = bb;
    }
}

// ============ k_conv2: folded 1x1 conv (128->32), conflict-free ws, f32x2 =======
// grid 4096 = (n,y). 256 thr = 64 pxgroups(4px) x 4 ogroups(8o). [profiled launch]
__global__ __launch_bounds__(256) void k_conv2(){
    __shared__ __align__(16) u64 ws[2048];   // ws[cp*32 + o]
    __shared__ float bs[32];
    int n = blockIdx.x >> 8, y = blockIdx.x & 255;
    for (int i = threadIdx.x; i < 2048; i += 256) ws[i] = g_w2p[n*2048 + i];
    if (threadIdx.x < 32) bs[threadIdx.x] = g_b2[n*32 + threadIdx.x];
    __syncthreads();
    int pxg = threadIdx.x >> 2, og = threadIdx.x & 3;
    const float* inb = g_r + ((size_t)(n*256 + y)*256 + pxg*4)*128;
    u64 acc[4][8];
    #pragma unroll
    for (int p = 0; p < 4; p++)
        #pragma unroll
        for (int j = 0; j < 8; j++) acc[p][j] = 0ull;
    #pragma unroll 2
    for (int cc = 0; cc < 128; cc += 4){
        F4U a[4];
        #pragma unroll
        for (int p = 0; p < 4; p++) a[p].f = *(const float4*)(inb + p*128 + cc);
        int cp = cc >> 1;
        const u64* wp0 = &ws[cp*32 + og*8];
        const u64* wp1 = &ws[(cp+1)*32 + og*8];
        #pragma unroll
        for (int j2 = 0; j2 < 4; j2++){
            ulonglong2 w0 = *(const ulonglong2*)(wp0 + j2*2);   // cpair cp,  o = og*8+2j2, +1
            ulonglong2 w1 = *(const ulonglong2*)(wp1 + j2*2);   // cpair cp+1
            #pragma unroll
            for (int p = 0; p < 4; p++){
                ffma2(acc[p][2*j2],   a[p].u[0], w0.x);
                ffma2(acc[p][2*j2+1], a[p].u[0], w0.y);
                ffma2(acc[p][2*j2],   a[p].u[1], w1.x);
                ffma2(acc[p][2*j2+1], a[p].u[1], w1.y);
            }
        }
    }
    int x0 = pxg*4;
    #pragma unroll
    for (int j = 0; j < 8; j++){
        int o = og*8 + j;
        float bb = bs[o];
        float2 f0 = up2(acc[0][j]), f1 = up2(acc[1][j]), f2 = up2(acc[2][j]), f3 = up2(acc[3][j]);
        float4 r4 = make_float4(f0.x+f0.y+bb, f1.x+f1.y+bb, f2.x+f2.y+bb, f3.x+f3.y+bb);
        *(float4*)(g_lg + ((size_t)(n*32 + o)*256 + y)*256 + x0) = r4;
    }
}

// ============ k_softx: per-row softmax+cumsum (channel 2*hd) -> gy coord ========
__global__ __launch_bounds__(256) void k_softx(){
    int lane = threadIdx.x & 31, wid = threadIdx.x >> 5;
    int R = blockIdx.x*8 + wid;
    int p = R >> 8, y = R & 255;
    int n = p >> 4, hd = p & 15;
    const float* src = g_lg + ((size_t)(n*32 + 2*hd)*256 + y)*256 + lane*8;
    float v[8];
    {
        float4 A = *(const float4*)src, B = *(const float4*)(src + 4);
        v[0]=A.x; v[1]=A.y; v[2]=A.z; v[3]=A.w;
        v[4]=B.x; v[5]=B.y; v[6]=B.z; v[7]=B.w;
    }
    float m = v[0];
    #pragma unroll
    for (int i = 1; i < 8; i++) m = fmaxf(m, v[i]);
    #pragma unroll
    for (int off = 16; off >= 1; off >>= 1) m = fmaxf(m, __shfl_xor_sync(FULL, m, off));
    float ls = 0.f;
    #pragma unroll
    for (int i = 0; i < 8; i++){ v[i] = expf(v[i] - m); ls += v[i]; }
    float pre = ls;
    #pragma unroll
    for (int off = 1; off < 32; off <<= 1){
        float t = __shfl_up_sync(FULL, pre, off);
        if (lane >= off) pre += t;
    }
    float total = __shfl_sync(FULL, pre, 31);
    float run = pre - ls;
    float sc = 255.f / total;
    float o[8];
    #pragma unroll
    for (int i = 0; i < 8; i++){ run += v[i]; o[i] = run * sc; }
    float* dst = g_gy + (size_t)p*65536 + y*256 + lane*8;
    *(float4*)dst       = make_float4(o[0], o[1], o[2], o[3]);
    *(float4*)(dst + 4) = make_float4(o[4], o[5], o[6], o[7]);
}

// ============ k_softy: per-col softmax+cumsum, 4 row-chunks x 1024 thr ==========
__global__ __launch_bounds__(1024) void k_softy(){
    __shared__ float pm[4][256], ps[4][256];
    int pb = blockIdx.x;
    int n = pb >> 4, hd = pb & 15;
    int col = threadIdx.x & 255, ch = threadIdx.x >> 8;
    const float* src = g_lg + ((size_t)(n*32 + 2*hd + 1)*256)*256 + col;
    float m = -1e30f;
    for (int y = ch*64; y < ch*64 + 64; y++) m = fmaxf(m, __ldg(src + (size_t)y*256));
    pm[ch][col] = m; __syncthreads();
    m = fmaxf(fmaxf(pm[0][col], pm[1][col]), fmaxf(pm[2][col], pm[3][col]));
    float s = 0.f;
    for (int y = ch*64; y < ch*64 + 64; y++) s += expf(__ldg(src + (size_t)y*256) - m);
    ps[ch][col] = s; __syncthreads();
    float tot = ps[0][col] + ps[1][col] + ps[2][col] + ps[3][col];
    float run = 0.f;
    for (int k = 0; k < 4; k++) if (k < ch) run += ps[k][col];
    float sc = 255.f / tot;
    float* dst = g_gx + (size_t)pb*65536 + col;
    for (int y = ch*64; y < ch*64 + 64; y++){
        run += expf(__ldg(src + (size_t)y*256) - m);
        dst[(size_t)y*256] = run * sc;
    }
}

// ============ k_sample: 32x32 tiles, lanes along y (coalesced gathers) ==========
__global__ __launch_bounds__(256) void k_sample(const float* __restrict__ hi,
                                                float* __restrict__ out){
    __shared__ float sgx[32][33], sgy[32][33], so[32][33];
    int b = blockIdx.x;
    int p = b >> 6, tile = b & 63;
    int y0 = (tile >> 3) * 32, x0 = (tile & 7) * 32;
    size_t base = (size_t)p*65536;
    {
        int row = threadIdx.x >> 3, c4 = (threadIdx.x & 7) * 4;
        size_t idx = base + (size_t)(y0 + row)*256 + x0 + c4;
        float4 a = *(const float4*)(g_gx + idx);
        float4 c = *(const float4*)(g_gy + idx);
        sgx[row][c4]=a.x; sgx[row][c4+1]=a.y; sgx[row][c4+2]=a.z; sgx[row][c4+3]=a.w;
        sgy[row][c4]=c.x; sgy[row][c4+1]=c.y; sgy[row][c4+2]=c.z; sgy[row][c4+3]=c.w;
    }
    __syncthreads();
    const float* s = hi + base;
    int yl = threadIdx.x & 31, xg = threadIdx.x >> 5;
    #pragma unroll
    for (int k = 0; k < 4; k++){
        int xl = xg*4 + k;
        float gx = sgx[yl][xl], gy = sgy[yl][xl];
        float xf = floorf(gx), yf = floorf(gy);
        float wx = gx - xf, wy = gy - yf;
        int ix0 = (int)xf, iy0 = (int)yf;
        int ix1 = ix0 + 1, iy1 = iy0 + 1;
        float mx0 = (ix0 >= 0 && ix0 <= 255) ? 1.f : 0.f;
        float mx1 = (ix1 >= 0 && ix1 <= 255) ? 1.f : 0.f;
        float my0 = (iy0 >= 0 && iy0 <= 255) ? 1.f : 0.f;
        float my1 = (iy1 >= 0 && iy1 <= 255) ? 1.f : 0.f;
        int cx0 = min(max(ix0, 0), 255), cx1 = min(max(ix1, 0), 255);
        int cy0 = min(max(iy0, 0), 255), cy1 = min(max(iy1, 0), 255);
        float v00 = __ldg(s + (size_t)cy0*256 + cx0);
        float v10 = __ldg(s + (size_t)cy0*256 + cx1);
        float v01 = __ldg(s + (size_t)cy1*256 + cx0);
        float v11 = __ldg(s + (size_t)cy1*256 + cx1);
        so[yl][xl] = v00*((1.f-wx)*(1.f-wy)*mx0*my0)
                   + v10*(wx*(1.f-wy)*mx1*my0)
                   + v01*((1.f-wx)*wy*mx0*my1)
                   + v11*(wx*wy*mx1*my1);
    }
    __syncthreads();
    {
        int row = threadIdx.x >> 3, c4 = (threadIdx.x & 7) * 4;
        size_t idx = base + (size_t)(y0 + row)*256 + x0 + c4;
        *(float4*)(out + idx) = make_float4(so[row][c4], so[row][c4+1],
                                            so[row][c4+2], so[row][c4+3]);
    }
}

// ================================ launch ========================================
extern "C" void kernel_launch(void* const* d_in, const int* in_sizes, int n_in,
                              void* d_out, int out_size){
    const float* lowres  = (const float*)d_in[0];
    const float* highres = (const float*)d_in[1];
    const float* conv1_w = (const float*)d_in[2];
    const float* conv1_b = (const float*)d_in[3];
    const float* gn_w    = (const float*)d_in[4];
    const float* gn_b    = (const float*)d_in[5];
    const float* se_w1   = (const float*)d_in[6];
    const float* se_w2   = (const float*)d_in[7];
    const float* conv2_w = (const float*)d_in[8];
    float* out = (float*)d_out;

    k_trconv1<<<dim3(2048, 2), 256>>>(lowres, conv1_w, conv1_b);  // 1
    k_up     <<<4096, 256>>>();                                   // 2
    k_fold   <<<16, 1024>>>(gn_w, gn_b, se_w1, se_w2, conv2_w);   // 3
    k_conv2  <<<4096, 256>>>();                                   // 4  <- ncu captures this
    k_softx  <<<8192, 256>>>();                                   // 5
    k_softy  <<<256, 1024>>>();                                   // 6
    k_sample <<<16384, 256>>>(highres, out);                      // 7
}